// round 10
// baseline (speedup 1.0000x reference)
#include <cuda_runtime.h>

// SpatialTransformer 3D trilinear resample. B=4, H=W=D=128, C=2, fp32.
//
// R9: revert R5's x-merge (FAILED: LDG.128 4-wf floor + ALU/occupancy cost).
// Back to R4 structure (lane varies j/x for near-coalesced gathers, smem
// transpose, lane varies k for coalesced stores, 2-deep load pipeline), plus:
//  - persistent multi-tile blocks: grid=512, each block owns 16 tiles of ONE
//    batch b -> theta constants hoisted out of the tile loop
//  - cross-tile pipelining: after the per-tile sync, next tile's first two
//    load-stages are issued BEFORE the current tile's smem+STG store phase,
//    hiding the store under gather latency and killing the pipeline tail
//  - double-buffered smem tile, one __syncthreads per tile
//
// Reference conventions reproduced exactly: full-extent pixel mapping,
// clip-then-float corners, flat index y*W + z*W*H + x, far-slab weight
// (z1f - z0f). Numerics identical to R4 (rel_err 5.27e-4).

#define HH 128
#define WW 128
#define DD 128
#define NPB (HH * WW * DD)      // 2097152
#define TILES_PER_B 2048        // 4 k-tiles * 4 j-tiles * 128 i
#define BLOCKS_PER_B 128
#define TILES_PER_BLOCK (TILES_PER_B / BLOCKS_PER_B)   // 16

struct Stage {
    float2 pa, pb, pc, pd, pe, pf, pg, ph;
    float wx1, wx0, wy1, wy0, wzA, wzB;
};

__device__ __forceinline__ void stage_load(
    const float2* __restrict__ im2,
    float t2, float t6, float t10,
    float cx, float cy, float cz,
    int k0, int kl, Stage& sg)
{
    const float s = 2.0f / 127.0f;
    const float zg = fmaf((float)(k0 + kl), s, -1.0f);

    const float px = (fmaf(t2,  zg, cx) + 1.0f) * 64.0f;
    const float py = (fmaf(t6,  zg, cy) + 1.0f) * 64.0f;
    const float pz = (fmaf(t10, zg, cz) + 1.0f) * 64.0f;

    const int fx = __float2int_rd(px);
    const int fy = __float2int_rd(py);
    const int fz = __float2int_rd(pz);

    const int x0 = min(max(fx,     0), WW - 1);
    const int x1 = min(max(fx + 1, 0), WW - 1);
    const int y0 = min(max(fy,     0), HH - 1);
    const int y1 = min(max(fy + 1, 0), HH - 1);
    const int z0 = min(max(fz,     0), DD - 1);
    const int z1 = min(max(fz + 1, 0), DD - 1);

    // reference flat convention: y*W + z*(W*H) + x
    const int p00 = y0 * WW + z0 * (WW * HH) + x0;
    const int dx  = x1 - x0;
    const int dy  = (y1 - y0) * WW;
    const int dz  = (z1 - z0) * (WW * HH);

    const float2* a = im2 + p00;
    sg.pa = __ldg(a);
    sg.pc = __ldg(a + dx);
    sg.pb = __ldg(a + dy);
    sg.pd = __ldg(a + dy + dx);
    const float2* e = a + dz;
    sg.pe = __ldg(e);
    sg.pg = __ldg(e + dx);
    sg.pf = __ldg(e + dy);
    sg.ph = __ldg(e + dy + dx);

    const float x0f = (float)x0, x1f = (float)x1;
    const float y0f = (float)y0, y1f = (float)y1;
    const float z0f = (float)z0, z1f = (float)z1;

    sg.wx1 = x1f - px;  sg.wx0 = px - x0f;
    sg.wy1 = y1f - py;  sg.wy0 = py - y0f;
    sg.wzA = z1f - pz;                 // near slab (z1f - z)
    sg.wzB = z1f - z0f;                // far slab  (z1f - z0f) — ref convention
}

__device__ __forceinline__ float2 stage_math(const Stage& sg)
{
    float2 r;
    r.x = sg.wzA * (sg.wy1 * fmaf(sg.wx1, sg.pa.x, sg.wx0 * sg.pc.x)
                  + sg.wy0 * fmaf(sg.wx1, sg.pb.x, sg.wx0 * sg.pd.x))
        + sg.wzB * (sg.wy1 * fmaf(sg.wx1, sg.pe.x, sg.wx0 * sg.pg.x)
                  + sg.wy0 * fmaf(sg.wx1, sg.pf.x, sg.wx0 * sg.ph.x));
    r.y = sg.wzA * (sg.wy1 * fmaf(sg.wx1, sg.pa.y, sg.wx0 * sg.pc.y)
                  + sg.wy0 * fmaf(sg.wx1, sg.pb.y, sg.wx0 * sg.pd.y))
        + sg.wzB * (sg.wy1 * fmaf(sg.wx1, sg.pe.y, sg.wx0 * sg.pg.y)
                  + sg.wy0 * fmaf(sg.wx1, sg.pf.y, sg.wx0 * sg.ph.y));
    return r;
}

__global__ __launch_bounds__(256, 4) void st3d_kernel(
    const float* __restrict__ image,   // [B, H, W, D, C] flat, C=2
    const float* __restrict__ theta,   // [B, 3, 4]
    float2* __restrict__ out)          // [B*N] float2
{
    __shared__ float2 buf[2][32][33];  // double-buffered transpose tile

    const int tid  = threadIdx.x;
    const int lane = tid & 31;
    const int wid  = tid >> 5;

    // grid = 512: b = bx>>7 fixed per block; 16 tiles t = (bx&127) + 128*mi
    const unsigned bx = blockIdx.x;
    const int b = bx >> 7;

    const float* th = theta + b * 12;
    const float t0  = __ldg(th + 0),  t1  = __ldg(th + 1),  t2  = __ldg(th + 2),  t3  = __ldg(th + 3);
    const float t4  = __ldg(th + 4),  t5  = __ldg(th + 5),  t6  = __ldg(th + 6),  t7  = __ldg(th + 7);
    const float t8  = __ldg(th + 8),  t9  = __ldg(th + 9),  t10 = __ldg(th + 10), t11 = __ldg(th + 11);

    const float s = 2.0f / 127.0f;
    const float2* __restrict__ im2 = (const float2*)image + (size_t)b * NPB;
    float2* __restrict__ outb = out + (size_t)b * NPB;

    // per-tile context
    int t = bx & 127;
    int k0; float cx, cy, cz; float2* op;
    {
        k0 = (t & 3) << 5;
        const int j0 = ((t >> 2) & 3) << 5;
        const int i  = t >> 4;
        const float xg = fmaf((float)(j0 + lane), s, -1.0f);
        const float yg = fmaf((float)i, s, -1.0f);
        cx = fmaf(t0, xg, fmaf(t1, yg, t3));
        cy = fmaf(t4, xg, fmaf(t5, yg, t7));
        cz = fmaf(t8, xg, fmaf(t9, yg, t11));
        op = outb + i * (WW * DD) + j0 * DD + k0;
    }

    Stage s0, s1;
    stage_load(im2, t2, t6, t10, cx, cy, cz, k0, wid,     s0);
    stage_load(im2, t2, t6, t10, cx, cy, cz, k0, wid + 8, s1);

    int p = 0;
    #pragma unroll 1
    for (int mi = 0; ; mi++) {
        // interleaved math/load (R4 pattern); kl is static per position
        buf[p][lane][wid     ] = stage_math(s0);
        stage_load(im2, t2, t6, t10, cx, cy, cz, k0, wid + 16, s0);
        buf[p][lane][wid +  8] = stage_math(s1);
        stage_load(im2, t2, t6, t10, cx, cy, cz, k0, wid + 24, s1);
        buf[p][lane][wid + 16] = stage_math(s0);
        buf[p][lane][wid + 24] = stage_math(s1);

        __syncthreads();

        float2* op_cur = op;
        const int pcur = p;
        const bool last = (mi == TILES_PER_BLOCK - 1);

        if (!last) {
            // next tile context + prefetch its first two load-stages
            t += 128;
            k0 = (t & 3) << 5;
            const int j0 = ((t >> 2) & 3) << 5;
            const int i  = t >> 4;
            const float xg = fmaf((float)(j0 + lane), s, -1.0f);
            const float yg = fmaf((float)i, s, -1.0f);
            cx = fmaf(t0, xg, fmaf(t1, yg, t3));
            cy = fmaf(t4, xg, fmaf(t5, yg, t7));
            cz = fmaf(t8, xg, fmaf(t9, yg, t11));
            op = outb + i * (WW * DD) + j0 * DD + k0;

            stage_load(im2, t2, t6, t10, cx, cy, cz, k0, wid,     s0);
            stage_load(im2, t2, t6, t10, cx, cy, cz, k0, wid + 8, s1);
        }

        // store current tile (overlaps with prefetched gathers): lane varies k
        #pragma unroll
        for (int it = 0; it < 4; it++) {
            const int jl = wid + 8 * it;
            op_cur[jl * DD + lane] = buf[pcur][jl][lane];
        }

        if (last) break;
        p ^= 1;
    }
}

extern "C" void kernel_launch(void* const* d_in, const int* in_sizes, int n_in,
                              void* d_out, int out_size) {
    const float* image = (const float*)d_in[0];
    const float* theta = (const float*)d_in[1];
    float2* out = (float2*)d_out;

    st3d_kernel<<<512, 256>>>(image, theta, out);
}

// round 12
// speedup vs baseline: 1.2125x; 1.2125x over previous
#include <cuda_runtime.h>

// SpatialTransformer 3D trilinear resample. B=4, H=W=D=128, C=2, fp32.
//
// R11 = R4 (best: 55.5us) with the software pipeline deepened 2 -> 3 stages:
// up to 24 LDG.64 in flight per warp. launch_bounds(256,3) -> 85-reg cap.
//  - lane varies j (x): near-coalesced gathers (affine near-identity)
//  - smem 32x33 transpose tile; store phase lane varies k: coalesced 256B STG
//  - coordinate math EXACTLY as R4 (reference is discontinuous at integer z
//    crossings due to its (z1f - z0f) far-slab weight; don't re-associate)
//
// Reference conventions reproduced exactly: full-extent pixel mapping,
// clip-then-float corners, flat index y*W + z*W*H + x, far-slab weight
// (z1f - z0f).

#define HH 128
#define WW 128
#define DD 128
#define NPB (HH * WW * DD)      // 2097152

struct Stage {
    float2 pa, pb, pc, pd, pe, pf, pg, ph;
    float wx1, wx0, wy1, wy0, wzA, wzB;
};

__device__ __forceinline__ void stage_load(
    const float2* __restrict__ im2,
    float t2, float t6, float t10,
    float cx, float cy, float cz,
    int k0, int kl, Stage& sg)
{
    const float s = 2.0f / 127.0f;
    const float zg = fmaf((float)(k0 + kl), s, -1.0f);

    const float px = (fmaf(t2,  zg, cx) + 1.0f) * 64.0f;
    const float py = (fmaf(t6,  zg, cy) + 1.0f) * 64.0f;
    const float pz = (fmaf(t10, zg, cz) + 1.0f) * 64.0f;

    const int fx = __float2int_rd(px);
    const int fy = __float2int_rd(py);
    const int fz = __float2int_rd(pz);

    const int x0 = min(max(fx,     0), WW - 1);
    const int x1 = min(max(fx + 1, 0), WW - 1);
    const int y0 = min(max(fy,     0), HH - 1);
    const int y1 = min(max(fy + 1, 0), HH - 1);
    const int z0 = min(max(fz,     0), DD - 1);
    const int z1 = min(max(fz + 1, 0), DD - 1);

    // reference flat convention: y*W + z*(W*H) + x
    const int p00 = y0 * WW + z0 * (WW * HH) + x0;
    const int dx  = x1 - x0;
    const int dy  = (y1 - y0) * WW;
    const int dz  = (z1 - z0) * (WW * HH);

    const float2* a = im2 + p00;
    sg.pa = __ldg(a);
    sg.pc = __ldg(a + dx);
    sg.pb = __ldg(a + dy);
    sg.pd = __ldg(a + dy + dx);
    const float2* e = a + dz;
    sg.pe = __ldg(e);
    sg.pg = __ldg(e + dx);
    sg.pf = __ldg(e + dy);
    sg.ph = __ldg(e + dy + dx);

    const float x0f = (float)x0, x1f = (float)x1;
    const float y0f = (float)y0, y1f = (float)y1;
    const float z0f = (float)z0, z1f = (float)z1;

    sg.wx1 = x1f - px;  sg.wx0 = px - x0f;
    sg.wy1 = y1f - py;  sg.wy0 = py - y0f;
    sg.wzA = z1f - pz;                 // near slab (z1f - z)
    sg.wzB = z1f - z0f;                // far slab  (z1f - z0f) — ref convention
}

__device__ __forceinline__ float2 stage_math(const Stage& sg)
{
    float2 r;
    r.x = sg.wzA * (sg.wy1 * fmaf(sg.wx1, sg.pa.x, sg.wx0 * sg.pc.x)
                  + sg.wy0 * fmaf(sg.wx1, sg.pb.x, sg.wx0 * sg.pd.x))
        + sg.wzB * (sg.wy1 * fmaf(sg.wx1, sg.pe.x, sg.wx0 * sg.pg.x)
                  + sg.wy0 * fmaf(sg.wx1, sg.pf.x, sg.wx0 * sg.ph.x));
    r.y = sg.wzA * (sg.wy1 * fmaf(sg.wx1, sg.pa.y, sg.wx0 * sg.pc.y)
                  + sg.wy0 * fmaf(sg.wx1, sg.pb.y, sg.wx0 * sg.pd.y))
        + sg.wzB * (sg.wy1 * fmaf(sg.wx1, sg.pe.y, sg.wx0 * sg.pg.y)
                  + sg.wy0 * fmaf(sg.wx1, sg.pf.y, sg.wx0 * sg.ph.y));
    return r;
}

__global__ __launch_bounds__(256, 3) void st3d_kernel(
    const float* __restrict__ image,   // [B, H, W, D, C] flat, C=2
    const float* __restrict__ theta,   // [B, 3, 4]
    float2* __restrict__ out)          // [B*N] float2
{
    __shared__ float2 tile[32][33];

    const int tid  = threadIdx.x;
    const int lane = tid & 31;
    const int wid  = tid >> 5;

    // grid: 4 k-tiles * 4 j-tiles * 128 i * 4 b = 8192 blocks
    const unsigned bx = blockIdx.x;
    const int k0 = (bx & 3) << 5;
    const int j0 = ((bx >> 2) & 3) << 5;
    const int i  = (bx >> 4) & 127;
    const int b  = bx >> 11;

    const float* t = theta + b * 12;
    const float t0  = __ldg(t + 0),  t1  = __ldg(t + 1),  t2  = __ldg(t + 2),  t3  = __ldg(t + 3);
    const float t4  = __ldg(t + 4),  t5  = __ldg(t + 5),  t6  = __ldg(t + 6),  t7  = __ldg(t + 7);
    const float t8  = __ldg(t + 8),  t9  = __ldg(t + 9),  t10 = __ldg(t + 10), t11 = __ldg(t + 11);

    const float s = 2.0f / 127.0f;
    const int j = j0 + lane;                       // lane varies x
    const float xg = fmaf((float)j, s, -1.0f);
    const float yg = fmaf((float)i, s, -1.0f);

    const float cx = fmaf(t0, xg, fmaf(t1, yg, t3));
    const float cy = fmaf(t4, xg, fmaf(t5, yg, t7));
    const float cz = fmaf(t8, xg, fmaf(t9, yg, t11));

    const float2* __restrict__ im2 = (const float2*)image + (size_t)b * NPB;

    // 3-deep software pipeline over the 4 k-iterations (kl = wid + 8*it)
    Stage s0, s1, s2;
    stage_load(im2, t2, t6, t10, cx, cy, cz, k0, wid,      s0);
    stage_load(im2, t2, t6, t10, cx, cy, cz, k0, wid + 8,  s1);
    stage_load(im2, t2, t6, t10, cx, cy, cz, k0, wid + 16, s2);

    tile[lane][wid]      = stage_math(s0);
    stage_load(im2, t2, t6, t10, cx, cy, cz, k0, wid + 24, s0);

    tile[lane][wid + 8]  = stage_math(s1);
    tile[lane][wid + 16] = stage_math(s2);
    tile[lane][wid + 24] = stage_math(s0);

    __syncthreads();

    // store phase: lane varies k -> coalesced 256B warp stores
    float2* __restrict__ op = out + (size_t)b * NPB + i * (WW * DD) + j0 * DD + k0;
    #pragma unroll
    for (int it = 0; it < 4; it++) {
        const int jl = wid + 8 * it;
        op[jl * DD + lane] = tile[jl][lane];
    }
}

extern "C" void kernel_launch(void* const* d_in, const int* in_sizes, int n_in,
                              void* d_out, int out_size) {
    const float* image = (const float*)d_in[0];
    const float* theta = (const float*)d_in[1];
    float2* out = (float2*)d_out;

    st3d_kernel<<<8192, 256>>>(image, theta, out);
}

// round 13
// speedup vs baseline: 1.3042x; 1.0756x over previous
#include <cuda_runtime.h>

// SpatialTransformer 3D trilinear resample. B=4, H=W=D=128, C=2, fp32.
//
// R13 = R4 (best, 55.5us) with the Stage slimmed for occupancy:
//  - stage stores only the 8 float2 payloads + (px,py,pz); floors/clamps/
//    weights recomputed in the math phase via the float path (bit-identical
//    for the value range here; validated in R5: rel_err unchanged)
//  - __launch_bounds__(256,5) -> 48-reg cap -> 5 blocks/SM, ~40 warps
//  - 2-deep pipeline (R11 showed deeper pipelines LOSE to more warps)
//  - lane varies j (x): near-coalesced gathers; smem 32x33 transpose tile;
//    store phase lane varies k: coalesced 256B STG
//
// Reference conventions reproduced exactly: full-extent pixel mapping,
// clip-then-float corners, flat index y*W + z*W*H + x, far-slab weight
// (z1f - z0f).

#define HH 128
#define WW 128
#define DD 128
#define NPB (HH * WW * DD)      // 2097152

struct Stage {
    float2 pa, pb, pc, pd, pe, pf, pg, ph;
    float px, py, pz;
};

__device__ __forceinline__ void stage_load(
    const float2* __restrict__ im2,
    float t2, float t6, float t10,
    float cx, float cy, float cz,
    int k0, int kl, Stage& sg)
{
    const float s = 2.0f / 127.0f;
    const float zg = fmaf((float)(k0 + kl), s, -1.0f);

    const float px = (fmaf(t2,  zg, cx) + 1.0f) * 64.0f;
    const float py = (fmaf(t6,  zg, cy) + 1.0f) * 64.0f;
    const float pz = (fmaf(t10, zg, cz) + 1.0f) * 64.0f;
    sg.px = px; sg.py = py; sg.pz = pz;

    const int fx = __float2int_rd(px);
    const int fy = __float2int_rd(py);
    const int fz = __float2int_rd(pz);

    const int x0 = min(max(fx,     0), WW - 1);
    const int x1 = min(max(fx + 1, 0), WW - 1);
    const int y0 = min(max(fy,     0), HH - 1);
    const int y1 = min(max(fy + 1, 0), HH - 1);
    const int z0 = min(max(fz,     0), DD - 1);
    const int z1 = min(max(fz + 1, 0), DD - 1);

    // reference flat convention: y*W + z*(W*H) + x
    const int p00 = y0 * WW + z0 * (WW * HH) + x0;
    const int dx  = x1 - x0;
    const int dy  = (y1 - y0) * WW;
    const int dz  = (z1 - z0) * (WW * HH);

    const float2* a = im2 + p00;
    sg.pa = __ldg(a);
    sg.pc = __ldg(a + dx);
    sg.pb = __ldg(a + dy);
    sg.pd = __ldg(a + dy + dx);
    const float2* e = a + dz;
    sg.pe = __ldg(e);
    sg.pg = __ldg(e + dx);
    sg.pf = __ldg(e + dy);
    sg.ph = __ldg(e + dy + dx);
}

__device__ __forceinline__ float2 stage_math(const Stage& sg)
{
    const float px = sg.px, py = sg.py, pz = sg.pz;

    // float-path floor/clamp: exact for this value range (~[-13, 141]);
    // matches the load phase's int path bit-for-bit (validated in R5).
    const float fxf = floorf(px);
    const float fyf = floorf(py);
    const float fzf = floorf(pz);

    const float x0f = fminf(fmaxf(fxf,        0.0f), 127.0f);
    const float x1f = fminf(fmaxf(fxf + 1.0f, 0.0f), 127.0f);
    const float y0f = fminf(fmaxf(fyf,        0.0f), 127.0f);
    const float y1f = fminf(fmaxf(fyf + 1.0f, 0.0f), 127.0f);
    const float z0f = fminf(fmaxf(fzf,        0.0f), 127.0f);
    const float z1f = fminf(fmaxf(fzf + 1.0f, 0.0f), 127.0f);

    const float wx1 = x1f - px, wx0 = px - x0f;
    const float wy1 = y1f - py, wy0 = py - y0f;
    const float wzA = z1f - pz;            // near slab (z1f - z)
    const float wzB = z1f - z0f;           // far slab  (z1f - z0f) — ref convention

    float2 r;
    r.x = wzA * (wy1 * fmaf(wx1, sg.pa.x, wx0 * sg.pc.x)
               + wy0 * fmaf(wx1, sg.pb.x, wx0 * sg.pd.x))
        + wzB * (wy1 * fmaf(wx1, sg.pe.x, wx0 * sg.pg.x)
               + wy0 * fmaf(wx1, sg.pf.x, wx0 * sg.ph.x));
    r.y = wzA * (wy1 * fmaf(wx1, sg.pa.y, wx0 * sg.pc.y)
               + wy0 * fmaf(wx1, sg.pb.y, wx0 * sg.pd.y))
        + wzB * (wy1 * fmaf(wx1, sg.pe.y, wx0 * sg.pg.y)
               + wy0 * fmaf(wx1, sg.pf.y, wx0 * sg.ph.y));
    return r;
}

__global__ __launch_bounds__(256, 5) void st3d_kernel(
    const float* __restrict__ image,   // [B, H, W, D, C] flat, C=2
    const float* __restrict__ theta,   // [B, 3, 4]
    float2* __restrict__ out)          // [B*N] float2
{
    __shared__ float2 tile[32][33];

    const int tid  = threadIdx.x;
    const int lane = tid & 31;
    const int wid  = tid >> 5;

    // grid: 4 k-tiles * 4 j-tiles * 128 i * 4 b = 8192 blocks
    const unsigned bx = blockIdx.x;
    const int k0 = (bx & 3) << 5;
    const int j0 = ((bx >> 2) & 3) << 5;
    const int i  = (bx >> 4) & 127;
    const int b  = bx >> 11;

    const float* t = theta + b * 12;
    const float t0  = __ldg(t + 0),  t1  = __ldg(t + 1),  t2  = __ldg(t + 2),  t3  = __ldg(t + 3);
    const float t4  = __ldg(t + 4),  t5  = __ldg(t + 5),  t6  = __ldg(t + 6),  t7  = __ldg(t + 7);
    const float t8  = __ldg(t + 8),  t9  = __ldg(t + 9),  t10 = __ldg(t + 10), t11 = __ldg(t + 11);

    const float s = 2.0f / 127.0f;
    const float xg = fmaf((float)(j0 + lane), s, -1.0f);   // lane varies x
    const float yg = fmaf((float)i, s, -1.0f);

    const float cx = fmaf(t0, xg, fmaf(t1, yg, t3));
    const float cy = fmaf(t4, xg, fmaf(t5, yg, t7));
    const float cz = fmaf(t8, xg, fmaf(t9, yg, t11));

    const float2* __restrict__ im2 = (const float2*)image + (size_t)b * NPB;

    // 2-deep software pipeline over the 4 k-iterations (kl = wid + 8*it)
    Stage s0, s1;
    stage_load(im2, t2, t6, t10, cx, cy, cz, k0, wid,      s0);
    stage_load(im2, t2, t6, t10, cx, cy, cz, k0, wid + 8,  s1);

    tile[lane][wid]      = stage_math(s0);
    stage_load(im2, t2, t6, t10, cx, cy, cz, k0, wid + 16, s0);

    tile[lane][wid + 8]  = stage_math(s1);
    stage_load(im2, t2, t6, t10, cx, cy, cz, k0, wid + 24, s1);

    tile[lane][wid + 16] = stage_math(s0);
    tile[lane][wid + 24] = stage_math(s1);

    __syncthreads();

    // store phase: lane varies k -> coalesced 256B warp stores
    float2* __restrict__ op = out + (size_t)b * NPB + i * (WW * DD) + j0 * DD + k0;
    #pragma unroll
    for (int it = 0; it < 4; it++) {
        const int jl = wid + 8 * it;
        op[jl * DD + lane] = tile[jl][lane];
    }
}

extern "C" void kernel_launch(void* const* d_in, const int* in_sizes, int n_in,
                              void* d_out, int out_size) {
    const float* image = (const float*)d_in[0];
    const float* theta = (const float*)d_in[1];
    float2* out = (float2*)d_out;

    st3d_kernel<<<8192, 256>>>(image, theta, out);
}